// round 5
// baseline (speedup 1.0000x reference)
#include <cuda_runtime.h>
#include <cuda_bf16.h>
#include <cfloat>
#include <math.h>
#include <cstdint>

// Problem constants
#define BB   16
#define SS   8192
#define AD   512
#define KD   512
#define MTOT (BB * SS)

// ---------------------------------------------------------------------------
// Scratch globals
// ---------------------------------------------------------------------------
__device__ float         g_qp[BB * AD];
__device__ float         g_epart[4 * MTOT];
__device__ float         g_cpart[64 * BB * KD];
__device__ __nv_bfloat16 g_Bt_hi[AD * KD];   // n-major: [n][k] = hi(Wk[k][n])
__device__ __nv_bfloat16 g_Bt_lo[AD * KD];

// ---------------------------------------------------------------------------
// PTX helpers
// ---------------------------------------------------------------------------
__device__ __forceinline__ uint32_t smem_u32(const void* p) {
    uint32_t a;
    asm("{ .reg .u64 t; cvta.to.shared.u64 t, %1; cvt.u32.u64 %0, t; }" : "=r"(a) : "l"(p));
    return a;
}
__device__ __forceinline__ float tanh_fast(float x) {
    float y;
    asm("tanh.approx.f32 %0, %1;" : "=f"(y) : "f"(x));
    return y;
}
__device__ __forceinline__ void ldsm_x4(uint32_t* r, uint32_t addr) {
    asm volatile("ldmatrix.sync.aligned.m8n8.x4.shared.b16 {%0,%1,%2,%3}, [%4];"
                 : "=r"(r[0]), "=r"(r[1]), "=r"(r[2]), "=r"(r[3]) : "r"(addr));
}
__device__ __forceinline__ void mma16816(float* d, const uint32_t* a, const uint32_t* b) {
    asm volatile(
        "mma.sync.aligned.m16n8k16.row.col.f32.bf16.bf16.f32 "
        "{%0,%1,%2,%3}, {%4,%5,%6,%7}, {%8,%9}, {%0,%1,%2,%3};"
        : "+f"(d[0]), "+f"(d[1]), "+f"(d[2]), "+f"(d[3])
        : "r"(a[0]), "r"(a[1]), "r"(a[2]), "r"(a[3]), "r"(b[0]), "r"(b[1]));
}
#define CP_ASYNC16(dst, src) \
    asm volatile("cp.async.cg.shared.global [%0], [%1], 16;" :: "r"(dst), "l"(src) : "memory")
#define CP_COMMIT()  asm volatile("cp.async.commit_group;" ::: "memory")
#define CP_WAIT0()   asm volatile("cp.async.wait_group 0;" ::: "memory")

// ---------------------------------------------------------------------------
// Kernel 0: prep Wk -> n-major bf16 hi/lo   g_Bt[n*512+k]
// ---------------------------------------------------------------------------
__global__ void prep_wk_kernel(const float* __restrict__ Wk) {
    const int k = blockIdx.x;     // input dim
    const int n = threadIdx.x;    // attn dim
    const float x = Wk[k * AD + n];
    const __nv_bfloat16 hi = __float2bfloat16(x);
    const __nv_bfloat16 lo = __float2bfloat16(x - __bfloat162float(hi));
    g_Bt_hi[n * KD + k] = hi;
    g_Bt_lo[n * KD + k] = lo;
}

// ---------------------------------------------------------------------------
// Kernel 1: q projection
// ---------------------------------------------------------------------------
__global__ void qproj_kernel(const float* __restrict__ query,
                             const float* __restrict__ Wq) {
    __shared__ float qs[AD];
    const int b = blockIdx.x;
    const int a = threadIdx.x;
    qs[a] = query[b * AD + a];
    __syncthreads();
    float acc = 0.f;
    #pragma unroll 8
    for (int j = 0; j < AD; j++) acc += qs[j] * Wq[j * AD + a];
    g_qp[b * AD + a] = acc;
}

// ---------------------------------------------------------------------------
// Kernel 2: mma.sync bf16 3-term GEMM + fused tanh/v epilogue
//   grid (4 nt, 1024 mt), 256 threads = 8 warps (2 M x 4 N), warp 64x32
//   K chunk 32, DOUBLE-buffered SMEM, cp.async for B, reg-prefetch for A
// ---------------------------------------------------------------------------
#define PADK 40                     // 80B row stride, ldmatrix conflict-free
#define ARR_B  (128 * PADK * 2)     // 10240 bytes per array
#define STG_B  (4 * ARR_B)          // 40960 bytes per stage
#define OFF_AH 0
#define OFF_AL ARR_B
#define OFF_BH (2 * ARR_B)
#define OFF_BL (3 * ARR_B)
#define OFF_ERED (2 * STG_B)        // 81920
#define SMEM_DYN (OFF_ERED + 4 * 128 * 4)   // 83968

__global__ __launch_bounds__(256)
void score_gemm_mma(const float* __restrict__ keys,
                    const float* __restrict__ vvec) {
    extern __shared__ char smem[];
    const uint32_t sb = smem_u32(smem);

    const int tid = threadIdx.x;
    const int wid = tid >> 5;
    const int lid = tid & 31;
    const int wm  = wid & 1;        // warp M (2)
    const int wn  = wid >> 1;       // warp N (4)
    const int nt  = blockIdx.x;     // 0..3
    const int mt  = blockIdx.y;     // 0..1023
    const int m0  = mt * 128;
    const int b   = mt >> 6;

    // loader mapping: 512 granules of 8 elems; 2 per thread
    const int g0row = tid >> 2,         g0c = (tid & 3) * 8;
    const int g1row = (tid + 256) >> 2, g1c = ((tid + 256) & 3) * 8;

    const float* keysA = keys + (size_t)m0 * KD;
    const __nv_bfloat16* BtH = g_Bt_hi + (size_t)(nt * 128) * KD;
    const __nv_bfloat16* BtL = g_Bt_lo + (size_t)(nt * 128) * KD;

    // byte offsets of this thread's two store granules within an array
    const uint32_t st0 = (uint32_t)(g0row * PADK + g0c) * 2;
    const uint32_t st1 = (uint32_t)(g1row * PADK + g1c) * 2;

    float acc[4][4][4];
    #pragma unroll
    for (int i = 0; i < 4; i++)
        #pragma unroll
        for (int j = 0; j < 4; j++)
            #pragma unroll
            for (int e = 0; e < 4; e++) acc[i][j][e] = 0.f;

    float4 pa[4];

    // convert+store A granules from pa into stage
    auto storeA = [&](uint32_t stage_base) {
        #pragma unroll
        for (int h = 0; h < 2; h++) {
            const float* xs = (const float*)&pa[h * 2];
            uint4 hv, lv;
            __nv_bfloat162* hp = (__nv_bfloat162*)&hv;
            __nv_bfloat162* lp = (__nv_bfloat162*)&lv;
            #pragma unroll
            for (int p = 0; p < 4; p++) {
                const float x0 = xs[2 * p], x1 = xs[2 * p + 1];
                const __nv_bfloat16 h0 = __float2bfloat16(x0);
                const __nv_bfloat16 h1 = __float2bfloat16(x1);
                const __nv_bfloat16 l0 = __float2bfloat16(x0 - __bfloat162float(h0));
                const __nv_bfloat16 l1 = __float2bfloat16(x1 - __bfloat162float(h1));
                hp[p] = __nv_bfloat162(h0, h1);
                lp[p] = __nv_bfloat162(l0, l1);
            }
            const uint32_t so = h ? st1 : st0;
            *(uint4*)(smem + stage_base + OFF_AH + so) = hv;
            *(uint4*)(smem + stage_base + OFF_AL + so) = lv;
        }
    };
    auto loadA = [&](int ko) {
        const float* a0 = keysA + (size_t)g0row * KD + ko + g0c;
        const float* a1 = keysA + (size_t)g1row * KD + ko + g1c;
        pa[0] = *(const float4*)(a0);  pa[1] = *(const float4*)(a0 + 4);
        pa[2] = *(const float4*)(a1);  pa[3] = *(const float4*)(a1 + 4);
    };
    auto loadB = [&](uint32_t stage_base_u32, int ko) {
        const uint32_t d0 = stage_base_u32 + OFF_BH + st0;
        const uint32_t d1 = stage_base_u32 + OFF_BH + st1;
        const uint32_t d2 = stage_base_u32 + OFF_BL + st0;
        const uint32_t d3 = stage_base_u32 + OFF_BL + st1;
        CP_ASYNC16(d0, BtH + (size_t)g0row * KD + ko + g0c);
        CP_ASYNC16(d1, BtH + (size_t)g1row * KD + ko + g1c);
        CP_ASYNC16(d2, BtL + (size_t)g0row * KD + ko + g0c);
        CP_ASYNC16(d3, BtL + (size_t)g1row * KD + ko + g1c);
        CP_COMMIT();
    };

    // ---- prologue: fill stage 0 ----
    loadA(0);
    loadB(sb, 0);
    storeA(0);
    CP_WAIT0();
    __syncthreads();

    // precomputed fragment address components
    const int arow = wm * 64 + (lid & 15);
    const int acolh = (lid >> 4) << 3;
    const int brow = wn * 32 + ((lid >> 4) << 3) + (lid & 7);
    const int bcolh = ((lid >> 3) & 1) << 3;

    for (int kc = 0; kc < 16; kc++) {
        const uint32_t bufb = (uint32_t)(kc & 1) * STG_B;
        const uint32_t nbb  = bufb ^ STG_B;

        // issue next-chunk loads (overlap with MMA below)
        if (kc + 1 < 16) {
            loadB(sb + nbb, (kc + 1) * 32);
            loadA((kc + 1) * 32);
        }

        const uint32_t sAh = sb + bufb + OFF_AH;
        const uint32_t sAl = sb + bufb + OFF_AL;
        const uint32_t sBh = sb + bufb + OFF_BH;
        const uint32_t sBl = sb + bufb + OFF_BL;

        #pragma unroll
        for (int ks = 0; ks < 2; ks++) {
            const int kb = ks * 16;
            uint32_t ah[4][4], al[4][4];
            #pragma unroll
            for (int mf = 0; mf < 4; mf++) {
                const uint32_t off = (uint32_t)(((arow + mf * 16) * PADK + kb + acolh) * 2);
                ldsm_x4(ah[mf], sAh + off);
                ldsm_x4(al[mf], sAl + off);
            }
            uint32_t bh[4][2], bl[4][2];
            #pragma unroll
            for (int nf2 = 0; nf2 < 2; nf2++) {
                const uint32_t off = (uint32_t)(((brow + nf2 * 16) * PADK + kb + bcolh) * 2);
                uint32_t t[4];
                ldsm_x4(t, sBh + off);
                bh[2 * nf2][0] = t[0]; bh[2 * nf2][1] = t[1];
                bh[2 * nf2 + 1][0] = t[2]; bh[2 * nf2 + 1][1] = t[3];
                ldsm_x4(t, sBl + off);
                bl[2 * nf2][0] = t[0]; bl[2 * nf2][1] = t[1];
                bl[2 * nf2 + 1][0] = t[2]; bl[2 * nf2 + 1][1] = t[3];
            }
            #pragma unroll
            for (int mf = 0; mf < 4; mf++)
                #pragma unroll
                for (int nf = 0; nf < 4; nf++) {
                    mma16816(acc[mf][nf], ah[mf], bh[nf]);
                    mma16816(acc[mf][nf], al[mf], bh[nf]);
                    mma16816(acc[mf][nf], ah[mf], bl[nf]);
                }
        }

        if (kc + 1 < 16) {
            storeA(nbb);
            CP_WAIT0();
        }
        __syncthreads();
    }

    // ---- epilogue: e_partial[row] = sum over this block's 128 cols ----
    float qv[4][2], vv[4][2];
    #pragma unroll
    for (int nf = 0; nf < 4; nf++)
        #pragma unroll
        for (int j = 0; j < 2; j++) {
            const int col = nt * 128 + wn * 32 + nf * 8 + (lid & 3) * 2 + j;
            qv[nf][j] = g_qp[b * AD + col];
            vv[nf][j] = vvec[col];
        }

    float es[4][2];
    #pragma unroll
    for (int mf = 0; mf < 4; mf++)
        #pragma unroll
        for (int h = 0; h < 2; h++) {
            float s = 0.f;
            #pragma unroll
            for (int nf = 0; nf < 4; nf++) {
                s += tanh_fast(acc[mf][nf][2 * h + 0] + qv[nf][0]) * vv[nf][0];
                s += tanh_fast(acc[mf][nf][2 * h + 1] + qv[nf][1]) * vv[nf][1];
            }
            es[mf][h] = s;
        }
    #pragma unroll
    for (int off = 1; off <= 2; off <<= 1)
        #pragma unroll
        for (int mf = 0; mf < 4; mf++)
            #pragma unroll
            for (int h = 0; h < 2; h++)
                es[mf][h] += __shfl_xor_sync(0xffffffffu, es[mf][h], off);

    float (*e_red)[128] = (float (*)[128])(smem + OFF_ERED);
    if ((lid & 3) == 0) {
        const int gq = lid >> 2;
        #pragma unroll
        for (int mf = 0; mf < 4; mf++)
            #pragma unroll
            for (int h = 0; h < 2; h++)
                e_red[wn][wm * 64 + mf * 16 + h * 8 + gq] = es[mf][h];
    }
    __syncthreads();
    if (tid < 128)
        g_epart[nt * MTOT + m0 + tid] =
            e_red[0][tid] + e_red[1][tid] + e_red[2][tid] + e_red[3][tid];
}

// ---------------------------------------------------------------------------
// Kernel 3: masked softmax over S per batch (sums 4 partials)
// ---------------------------------------------------------------------------
__global__ __launch_bounds__(1024)
void softmax_kernel(const int* __restrict__ mask, float* __restrict__ out) {
    const int b = blockIdx.x;
    const int t = threadIdx.x;
    const int lane = t & 31;
    const int wid  = t >> 5;
    __shared__ float sred[32];

    float sc[8];
    #pragma unroll
    for (int r = 0; r < 8; r++) {
        const int s = t + r * 1024;
        float e = g_epart[0 * MTOT + b * SS + s]
                + g_epart[1 * MTOT + b * SS + s]
                + g_epart[2 * MTOT + b * SS + s]
                + g_epart[3 * MTOT + b * SS + s];
        if (mask[b * SS + s] == 0) e = -FLT_MAX;
        sc[r] = e;
    }

    float m = sc[0];
    #pragma unroll
    for (int r = 1; r < 8; r++) m = fmaxf(m, sc[r]);
    #pragma unroll
    for (int off = 16; off > 0; off >>= 1)
        m = fmaxf(m, __shfl_xor_sync(0xffffffffu, m, off));
    if (lane == 0) sred[wid] = m;
    __syncthreads();
    if (t < 32) {
        float x = sred[t];
        #pragma unroll
        for (int off = 16; off > 0; off >>= 1)
            x = fmaxf(x, __shfl_xor_sync(0xffffffffu, x, off));
        if (t == 0) sred[0] = x;
    }
    __syncthreads();
    m = sred[0];
    __syncthreads();

    float ex[8];
    float sum = 0.f;
    #pragma unroll
    for (int r = 0; r < 8; r++) {
        ex[r] = expf(sc[r] - m);
        sum += ex[r];
    }
    #pragma unroll
    for (int off = 16; off > 0; off >>= 1)
        sum += __shfl_xor_sync(0xffffffffu, sum, off);
    if (lane == 0) sred[wid] = sum;
    __syncthreads();
    if (t < 32) {
        float x = sred[t];
        #pragma unroll
        for (int off = 16; off > 0; off >>= 1)
            x += __shfl_xor_sync(0xffffffffu, x, off);
        if (t == 0) sred[0] = x;
    }
    __syncthreads();
    const float inv = 1.f / sred[0];

    #pragma unroll
    for (int r = 0; r < 8; r++)
        out[BB * KD + b * SS + t + r * 1024] = ex[r] * inv;
}

// ---------------------------------------------------------------------------
// Kernel 4: context partials
// ---------------------------------------------------------------------------
__global__ __launch_bounds__(256)
void ctx_part_kernel(const float* __restrict__ keys,
                     const float* __restrict__ aout) {
    const int scn = blockIdx.x;
    const int b   = blockIdx.y;
    const int t   = threadIdx.x;
    __shared__ float as[128];
    if (t < 128) as[t] = aout[b * SS + scn * 128 + t];
    __syncthreads();

    const float* kb = keys + ((size_t)b * SS + (size_t)scn * 128) * KD;
    float s0 = 0.f, s1 = 0.f;
    #pragma unroll 4
    for (int s = 0; s < 128; s++) {
        const float av = as[s];
        s0 += av * kb[(size_t)s * KD + t];
        s1 += av * kb[(size_t)s * KD + t + 256];
    }
    g_cpart[(scn * BB + b) * KD + t]       = s0;
    g_cpart[(scn * BB + b) * KD + t + 256] = s1;
}

// ---------------------------------------------------------------------------
// Kernel 5: reduce context partials
// ---------------------------------------------------------------------------
__global__ __launch_bounds__(512)
void ctx_reduce_kernel(float* __restrict__ out) {
    const int b = blockIdx.x;
    const int t = threadIdx.x;
    float s = 0.f;
    #pragma unroll 8
    for (int scn = 0; scn < 64; scn++)
        s += g_cpart[(scn * BB + b) * KD + t];
    out[b * KD + t] = s;
}

// ---------------------------------------------------------------------------
extern "C" void kernel_launch(void* const* d_in, const int* in_sizes, int n_in,
                              void* d_out, int out_size) {
    const float* query = (const float*)d_in[0];
    const float* keys  = (const float*)d_in[1];
    const int*   mask  = (const int*)  d_in[2];
    const float* Wq    = (const float*)d_in[3];
    const float* Wk    = (const float*)d_in[4];
    const float* v     = (const float*)d_in[5];
    float* out = (float*)d_out;

    static bool attr_set = false;
    if (!attr_set) {
        cudaFuncSetAttribute(score_gemm_mma,
                             cudaFuncAttributeMaxDynamicSharedMemorySize, SMEM_DYN);
        attr_set = true;
    }

    prep_wk_kernel<<<KD, AD>>>(Wk);
    qproj_kernel<<<BB, AD>>>(query, Wq);
    score_gemm_mma<<<dim3(4, 1024), 256, SMEM_DYN>>>(keys, v);
    softmax_kernel<<<BB, 1024>>>(mask, out);
    ctx_part_kernel<<<dim3(64, BB), 256>>>(keys, out + BB * KD);
    ctx_reduce_kernel<<<BB, 512>>>(out);
}